// round 14
// baseline (speedup 1.0000x reference)
#include <cuda_runtime.h>

// Problem constants
#define B_    2
#define C_    128
#define T_    4
#define S_    16384      // T*H*W
#define NH_   32
#define N_    1024       // T*h*w = 4*16*16
#define TABSZ 6727       // (2T-1)*(2h-1)*(2w-1) = 7*31*31
#define EPS_  1e-5f
#define LOG2E_ 1.4426950408889634f

// ---------------- scratch (static device globals; no runtime alloc) -------
__device__ float g_stat[3][B_][32][2];      // groupnorm sum / sumsq partials
__device__ float g_aff[3][B_][C_][2];       // per-channel affine (a, b)
__device__ float g_qp[B_][NH_][N_][4];      // pooled Q raw sums
__device__ float g_kp[B_][NH_][N_][4];      // pooled K raw sums
__device__ float g_vp[B_][NH_][N_][64];     // RAW V, tf32-rounded, vp layout
// bf16 split components (packed pairs along the K/channel dim)
__device__ unsigned g_w0[3][128][64];       // hi comp of W, bf16x2 (c,c+1)
__device__ unsigned g_w1[3][128][64];       // residual comp
__device__ unsigned g_x0[B_][64][S_];       // hi comp of x, bf16x2 (2cp,2cp+1)
__device__ unsigned g_x1[B_][64][S_];       // residual comp

// ---------------- mma / numeric helpers ------------------------------------
__device__ __forceinline__ unsigned tf32r(float f) {
    unsigned u; asm("cvt.rna.tf32.f32 %0, %1;" : "=r"(u) : "f"(f)); return u;
}
__device__ __forceinline__ void mma_tf32(float* d, unsigned a0, unsigned a1,
                                         unsigned a2, unsigned a3,
                                         unsigned b0, unsigned b1) {
    asm("mma.sync.aligned.m16n8k8.row.col.f32.tf32.tf32.f32 "
        "{%0,%1,%2,%3}, {%4,%5,%6,%7}, {%8,%9}, {%0,%1,%2,%3};"
        : "+f"(d[0]), "+f"(d[1]), "+f"(d[2]), "+f"(d[3])
        : "r"(a0), "r"(a1), "r"(a2), "r"(a3), "r"(b0), "r"(b1));
}
__device__ __forceinline__ void mma_bf16(float* d, unsigned a0, unsigned a1,
                                         unsigned a2, unsigned a3,
                                         unsigned b0, unsigned b1) {
    asm("mma.sync.aligned.m16n8k16.row.col.f32.bf16.bf16.f32 "
        "{%0,%1,%2,%3}, {%4,%5,%6,%7}, {%8,%9}, {%0,%1,%2,%3};"
        : "+f"(d[0]), "+f"(d[1]), "+f"(d[2]), "+f"(d[3])
        : "r"(a0), "r"(a1), "r"(a2), "r"(a3), "r"(b0), "r"(b1));
}
// pack two fp32 into bf16x2: low half = lo arg, high half = hi arg
__device__ __forceinline__ unsigned pack_bf16(float lo, float hi) {
    unsigned r;
    asm("cvt.rn.bf16x2.f32 %0, %1, %2;" : "=r"(r) : "f"(hi), "f"(lo));
    return r;
}
__device__ __forceinline__ float ex2f(float x) {
    float y; asm("ex2.approx.ftz.f32 %0, %1;" : "=f"(y) : "f"(x)); return y;
}

// ---------------- cp.async helpers ----------------------------------------
__device__ __forceinline__ void cp16(void* smem, const void* g) {
    unsigned sa = (unsigned)__cvta_generic_to_shared(smem);
    asm volatile("cp.async.cg.shared.global [%0], [%1], 16;" :: "r"(sa), "l"(g));
}
__device__ __forceinline__ void cp_commit() {
    asm volatile("cp.async.commit_group;");
}
__device__ __forceinline__ void cp_wait0() {
    asm volatile("cp.async.wait_group 0;" ::: "memory");
}
__device__ __forceinline__ void cp_wait1() {
    asm volatile("cp.async.wait_group 1;" ::: "memory");
}

// ================= K0: zero accumulators ===================================
__global__ void zero_kernel() {      // <<<512, 256>>>
    int idx = blockIdx.x * 256 + threadIdx.x;       // 0..131071
    float4 z = make_float4(0.f, 0.f, 0.f, 0.f);
    if (idx < 65536) ((float4*)g_qp)[idx] = z;
    else             ((float4*)g_kp)[idx - 65536] = z;
    if (idx < 96)    ((float4*)g_stat)[idx] = z;
}

// ================= K0b: bf16 split of W ====================================
__global__ void split_w_kernel(const float* __restrict__ Wq,
                               const float* __restrict__ Wk,
                               const float* __restrict__ Wv) {  // <<<96,256>>>
    int idx = blockIdx.x * 256 + threadIdx.x;      // 0..24575
    int pr = idx >> 13, rem = idx & 8191;          // 8192 = 128*64
    int o = rem >> 6, cp = rem & 63;
    const float* Wsel = (pr == 0) ? Wq : ((pr == 1) ? Wk : Wv);
    float vlo = Wsel[o * 128 + 2 * cp];
    float vhi = Wsel[o * 128 + 2 * cp + 1];
    unsigned p0 = pack_bf16(vlo, vhi);
    float rlo = vlo - __uint_as_float(p0 << 16);
    float rhi = vhi - __uint_as_float(p0 & 0xFFFF0000u);
    g_w0[pr][o][cp] = p0;
    g_w1[pr][o][cp] = pack_bf16(rlo, rhi);
}

// ================= K0c: bf16 split of x ====================================
__global__ __launch_bounds__(256) void split_x_kernel(
    const float* __restrict__ x) {                 // <<<2048,256>>>
    int idx = blockIdx.x * 256 + threadIdx.x;      // 0..524287
    int s4 = idx & 4095, cp = (idx >> 12) & 63, b = idx >> 18;
    const float* xlo = x + ((size_t)(b * 128 + 2 * cp)) * S_ + (s4 << 2);
    float4 vl = *(const float4*)xlo;
    float4 vh = *(const float4*)(xlo + S_);
    unsigned p0[4], p1[4];
    float l[4] = {vl.x, vl.y, vl.z, vl.w};
    float h[4] = {vh.x, vh.y, vh.z, vh.w};
#pragma unroll
    for (int i = 0; i < 4; i++) {
        p0[i] = pack_bf16(l[i], h[i]);
        float rl = l[i] - __uint_as_float(p0[i] << 16);
        float rh = h[i] - __uint_as_float(p0[i] & 0xFFFF0000u);
        p1[i] = pack_bf16(rl, rh);
    }
    *(uint4*)&g_x0[b][cp][s4 << 2] = make_uint4(p0[0], p0[1], p0[2], p0[3]);
    *(uint4*)&g_x1[b][cp][s4 << 2] = make_uint4(p1[0], p1[1], p1[2], p1[3]);
}

// ================= K1: projections via bf16-split tensor GEMM ==============
// Per CTA: 128 o x 64 s tile; K=128 in 4 chunks of 32c (16 kpairs),
// double-buffered cp.async of packed bf16x2 components.
// w*x ~= w0x0 + w0x1 + w1x0 (error ~2^-16); the three terms are issued as
// THREE SWEEPS over all 8 acc tiles so dependent MMAs are 8 apart.
#define WSTG (128 * 36)               // 4608 uints / stage
#define XSTG (2 * 16 * 72)            // 2304 uints / stage
#define SB_OFF (2 * WSTG + 2 * XSTG)  // 13824
#define PROJ_SMEM_FLOATS (SB_OFF + 512)
#define PROJ_SMEM_BYTES  (PROJ_SMEM_FLOATS * 4)

__global__ __launch_bounds__(256) void proj_kernel() {
    extern __shared__ float sm[];
    unsigned* Ws = (unsigned*)sm;
    unsigned* Xs = (unsigned*)sm + 2 * WSTG;
    float* sbuf  = sm + SB_OFF;

    const int pr  = blockIdx.z;
    const int b   = blockIdx.y;
    const int s_t = blockIdx.x << 6;
    const int tid = threadIdx.x;

    auto issue = [&](int kc, int st) {
        unsigned* wd = Ws + st * WSTG;
        unsigned* xd = Xs + st * XSTG;
#pragma unroll
        for (int j = 0; j < 4; j++) {          // W: 4096 uints = 1024 cp16
            int e = tid + 256 * j;
            int o = e >> 3, grp = e & 7;
            int comp = grp >> 2, seg = grp & 3;
            const unsigned* src = comp ? &g_w1[pr][o][kc * 16 + seg * 4]
                                       : &g_w0[pr][o][kc * 16 + seg * 4];
            cp16(wd + o * 36 + comp * 16 + seg * 4, src);
        }
#pragma unroll
        for (int j = 0; j < 2; j++) {          // X: 2048 uints = 512 cp16
            int e = tid + 256 * j;
            int comp = e >> 8, r = e & 255;
            int cp = r >> 4, seg = r & 15;
            const unsigned* src = comp ? &g_x1[b][kc * 16 + cp][s_t + seg * 4]
                                       : &g_x0[b][kc * 16 + cp][s_t + seg * 4];
            cp16(xd + comp * 1152 + cp * 72 + seg * 4, src);
        }
        cp_commit();
    };

    const int warp = tid >> 5, lane = tid & 31;
    const int gid = lane >> 2, tg = lane & 3;
    const int ow = warp >> 1, sw = warp & 1;
    const int o0 = ow << 5;
    const int sbase = sw << 5;

    float acc[2][4][4];
#pragma unroll
    for (int mb = 0; mb < 2; mb++)
#pragma unroll
        for (int nb = 0; nb < 4; nb++)
#pragma unroll
            for (int i = 0; i < 4; i++) acc[mb][nb][i] = 0.f;

    issue(0, 0);
    for (int kc = 0; kc < 4; kc++) {
        cp_wait0();
        __syncthreads();
        if (kc < 3) issue(kc + 1, (kc + 1) & 1);
        const unsigned* Wb = Ws + (kc & 1) * WSTG;
        const unsigned* Xb = Xs + (kc & 1) * XSTG;

#pragma unroll
        for (int ks2 = 0; ks2 < 2; ks2++) {
            const int kb = ks2 << 3;
            // B frags: b0 = kpair kb+tg, b1 = kpair kb+tg+4, col gid
            unsigned bx0[4][2], bx1[4][2];
#pragma unroll
            for (int nb = 0; nb < 4; nb++) {
                const unsigned* xc0 = Xb + (kb + tg) * 72 + sbase + nb * 8 + gid;
                bx0[nb][0] = xc0[0];
                bx0[nb][1] = xc0[4 * 72];
                const unsigned* xc1 = xc0 + 1152;
                bx1[nb][0] = xc1[0];
                bx1[nb][1] = xc1[4 * 72];
            }
            // A frags for both mb tiles, both components
            unsigned A0[2][4], A1[2][4];
#pragma unroll
            for (int mb = 0; mb < 2; mb++) {
                const unsigned* w0p = Wb + (o0 + mb * 16 + gid) * 36 + kb + tg;
                const unsigned* w1p = w0p + 16;
                A0[mb][0] = w0p[0];  A0[mb][1] = w0p[8 * 36];
                A0[mb][2] = w0p[4];  A0[mb][3] = w0p[8 * 36 + 4];
                A1[mb][0] = w1p[0];  A1[mb][1] = w1p[8 * 36];
                A1[mb][2] = w1p[4];  A1[mb][3] = w1p[8 * 36 + 4];
            }
            // three sweeps: dependent MMAs are 8 independent MMAs apart
#pragma unroll
            for (int mb = 0; mb < 2; mb++)
#pragma unroll
                for (int nb = 0; nb < 4; nb++)
                    mma_bf16(acc[mb][nb], A0[mb][0], A0[mb][1], A0[mb][2], A0[mb][3],
                             bx0[nb][0], bx0[nb][1]);
#pragma unroll
            for (int mb = 0; mb < 2; mb++)
#pragma unroll
                for (int nb = 0; nb < 4; nb++)
                    mma_bf16(acc[mb][nb], A0[mb][0], A0[mb][1], A0[mb][2], A0[mb][3],
                             bx1[nb][0], bx1[nb][1]);
#pragma unroll
            for (int mb = 0; mb < 2; mb++)
#pragma unroll
                for (int nb = 0; nb < 4; nb++)
                    mma_bf16(acc[mb][nb], A1[mb][0], A1[mb][1], A1[mb][2], A1[mb][3],
                             bx0[nb][0], bx0[nb][1]);
        }
        __syncthreads();
    }

    // ---- epilogue coordinates
    const int t  = s_t >> 12;
    const int hh = (s_t >> 6) & 63;
    const int y  = hh >> 2, sy = hh & 3;
    const int nbase = t * 256 + (y << 4);

    if (pr < 2) {
        float* dstp = (pr == 0) ? &g_qp[0][0][0][0] : &g_kp[0][0][0][0];
#pragma unroll
        for (int mb = 0; mb < 2; mb++) {
            const int cA = o0 + mb * 16 + gid, cB = cA + 8;
#pragma unroll
            for (int nb = 0; nb < 4; nb++) {
                float sA = acc[mb][nb][0] + acc[mb][nb][1];
                float sB = acc[mb][nb][2] + acc[mb][nb][3];
                sA += __shfl_xor_sync(0xffffffffu, sA, 1);
                sB += __shfl_xor_sync(0xffffffffu, sB, 1);
                if ((tg & 1) == 0) {
                    int n = nbase + (sw << 3) + (nb << 1) + (tg >> 1);
                    atomicAdd(dstp + (((size_t)(b * 32 + (cA >> 2)) * 1024 + n) << 2)
                                   + (cA & 3), sA);
                    atomicAdd(dstp + (((size_t)(b * 32 + (cB >> 2)) * 1024 + n) << 2)
                                   + (cB & 3), sB);
                }
            }
        }
    } else {
        float* Zs = sm;                      // 128 x 72 floats = 9216 < SB_OFF
#pragma unroll
        for (int mb = 0; mb < 2; mb++) {
            const int r = o0 + mb * 16 + gid;
#pragma unroll
            for (int nb = 0; nb < 4; nb++) {
                int col = sbase + nb * 8 + (tg << 1);
                *(float2*)&Zs[r * 72 + col]       = make_float2(acc[mb][nb][0], acc[mb][nb][1]);
                *(float2*)&Zs[(r + 8) * 72 + col] = make_float2(acc[mb][nb][2], acc[mb][nb][3]);
            }
        }
    }

    // ---- fused GroupNorm partial stats
#pragma unroll
    for (int mb = 0; mb < 2; mb++)
#pragma unroll
        for (int hi = 0; hi < 2; hi++) {
            float s = 0.f, s2 = 0.f;
#pragma unroll
            for (int nb = 0; nb < 4; nb++) {
                float v0 = acc[mb][nb][hi * 2 + 0];
                float v1 = acc[mb][nb][hi * 2 + 1];
                s += v0 + v1;
                s2 = fmaf(v0, v0, s2); s2 = fmaf(v1, v1, s2);
            }
            s  += __shfl_xor_sync(0xffffffffu, s, 1);
            s  += __shfl_xor_sync(0xffffffffu, s, 2);
            s2 += __shfl_xor_sync(0xffffffffu, s2, 1);
            s2 += __shfl_xor_sync(0xffffffffu, s2, 2);
            if (tg == 0) {
                int idx = (((warp << 3) | gid) << 3) | (mb << 2) | (hi << 1);
                sbuf[idx]     = s;
                sbuf[idx + 1] = s2;
            }
        }
    __syncthreads();

    if (pr == 2) {
        const float* Zs = sm;
#pragma unroll
        for (int j = 0; j < 8; j++) {
            int e = tid + (j << 8);
            int c = e >> 4, xq = e & 15;
            float4 v = *(const float4*)&Zs[c * 72 + (xq << 2)];
            float4 r = make_float4(
                __uint_as_float(tf32r(v.x)), __uint_as_float(tf32r(v.y)),
                __uint_as_float(tf32r(v.z)), __uint_as_float(tf32r(v.w)));
            *(float4*)&g_vp[b][c >> 2][nbase + xq][((c & 3) << 4) + (sy << 2)] = r;
        }
    }
    if (tid < 64) {
        int grp = tid >> 1, v = tid & 1;
        float tot = 0.f;
#pragma unroll
        for (int ci = 0; ci < 4; ci++) {
            int ch = (grp << 2) + ci;
            int cow = ch >> 5, r = ch & 31;
            int cmb = r >> 4, chi = (r >> 3) & 1, cgid = r & 7;
#pragma unroll
            for (int csw = 0; csw < 2; csw++) {
                int w2 = (cow << 1) | csw;
                tot += sbuf[(((w2 << 3) | cgid) << 3) | (cmb << 2) | (chi << 1) | v];
            }
        }
        atomicAdd(&g_stat[pr][b][grp][v], tot);
    }
}

// ================= K2: finalize stats -> per-channel affine ================
__global__ void finalize_stats(
    const float* __restrict__ gqg, const float* __restrict__ gqb,
    const float* __restrict__ gkg, const float* __restrict__ gkb,
    const float* __restrict__ gvg, const float* __restrict__ gvb) {   // <<<1,192>>>
    int i = threadIdx.x;
    int pr = i >> 6, r = i & 63, b = r >> 5, grp = r & 31;
    float s  = g_stat[pr][b][grp][0];
    float s2 = g_stat[pr][b][grp][1];
    float mean = s * (1.f / 65536.f);
    float var  = s2 * (1.f / 65536.f) - mean * mean;
    float rstd = rsqrtf(var + EPS_);
    const float* ga = (pr == 0) ? gqg : ((pr == 1) ? gkg : gvg);
    const float* be = (pr == 0) ? gqb : ((pr == 1) ? gkb : gvb);
#pragma unroll
    for (int d = 0; d < 4; d++) {
        int c = (grp << 2) + d;
        float a = rstd * ga[c];
        g_aff[pr][b][c][0] = a;
        g_aff[pr][b][c][1] = be[c] - mean * a;
    }
}

// ================= K3: fused tensor-core patch attention ===================
// Round-9 structure, minus the bound-softmax machinery: GN-normalized q/k
// keep logits small enough that 2^logit cannot over/underflow fp32, so
// w = ex2(q.k*HS + tab) directly, with tab folded into the dot's FMA chain.
#define VSP_    72
#define VS_BUF  (64 * VSP_)                 // 4608 floats per stage
#define SM_TAB  0
#define SM_K    6728                        // 1024 float4
#define SM_KC   (SM_K + 4096)               // 1024 ints
#define SM_VS   (SM_KC + 1024)              // 3 * 4608
#define ATTN_SMEM_FLOATS (SM_VS + 3 * VS_BUF)
#define ATTN_SMEM_BYTES (ATTN_SMEM_FLOATS * 4)

__global__ __launch_bounds__(256, 2) void attn_kernel(
    const float* __restrict__ rel_table, float* __restrict__ out) {
    extern __shared__ float sm[];
    float*  tab  = sm + SM_TAB;
    float4* ks4  = (float4*)(sm + SM_K);
    int*    kc   = (int*)(sm + SM_KC);
    float*  vsb0 = sm + SM_VS;

    const int b = blockIdx.z, g = blockIdx.y;
    const int n0 = blockIdx.x << 7;
    const int tid = threadIdx.x;

    // ---- kick off V chunks 0 and 1 immediately
#pragma unroll
    for (int st = 0; st < 2; st++) {
        const float* vsrc = &g_vp[b][g][st << 6][0];
        float* vdst = vsb0 + st * VS_BUF;
#pragma unroll
        for (int j = 0; j < 4; j++) {
            int idx = tid + 256 * j;
            int row = idx >> 4, seg = idx & 15;
            cp16(vdst + row * VSP_ + seg * 4, vsrc + row * 64 + seg * 4);
        }
        cp_commit();
    }

    // ---- load bias table (scaled by log2e) and normalized K + kc
    for (int i = tid; i < TABSZ; i += 256)
        tab[i] = rel_table[g * TABSZ + i] * LOG2E_;
    const float* afk = &g_aff[1][b][g << 2][0];     // [a0,b0,a1,b1,a2,b2,a3,b3]
    float4 afk0 = *(const float4*)afk;
    float4 afk1 = *(const float4*)(afk + 4);
    for (int i = tid; i < 1024; i += 256) {
        float4 kr = *(const float4*)&g_kp[b][g][i][0];
        float4 kk;
        kk.x = fmaf(kr.x * 0.0625f, afk0.x, afk0.y);
        kk.y = fmaf(kr.y * 0.0625f, afk0.z, afk0.w);
        kk.z = fmaf(kr.z * 0.0625f, afk1.x, afk1.y);
        kk.w = fmaf(kr.w * 0.0625f, afk1.z, afk1.w);
        ks4[i] = kk;
        kc[i]  = 961 * (i >> 8) + 31 * ((i >> 4) & 15) + (i & 15);
    }

    // ---- per-thread identity; q: normalize then scale to log2 domain
    const int warp = tid >> 5, lane = tid & 31;
    const int gid = lane >> 2, tg = lane & 3;
    const int r0 = (warp << 4) + gid;
    const int nq0 = n0 + r0, nq1 = nq0 + 8;
    const float* afq = &g_aff[0][b][g << 2][0];
    float4 afq0 = *(const float4*)afq;
    float4 afq1 = *(const float4*)(afq + 4);
    const float HS = 0.5f * LOG2E_;
    float4 qr0 = *(const float4*)&g_qp[b][g][nq0][0];
    float4 qr1 = *(const float4*)&g_qp[b][g][nq1][0];
    float4 q0, q1;
    q0.x = fmaf(qr0.x * 0.0625f, afq0.x, afq0.y) * HS;
    q0.y = fmaf(qr0.y * 0.0625f, afq0.z, afq0.w) * HS;
    q0.z = fmaf(qr0.z * 0.0625f, afq1.x, afq1.y) * HS;
    q0.w = fmaf(qr0.w * 0.0625f, afq1.z, afq1.w) * HS;
    q1.x = fmaf(qr1.x * 0.0625f, afq0.x, afq0.y) * HS;
    q1.y = fmaf(qr1.y * 0.0625f, afq0.z, afq0.w) * HS;
    q1.z = fmaf(qr1.z * 0.0625f, afq1.x, afq1.y) * HS;
    q1.w = fmaf(qr1.w * 0.0625f, afq1.z, afq1.w) * HS;
    const int cn0 = 961 * (nq0 >> 8) + 31 * ((nq0 >> 4) & 15) + (nq0 & 15) + 3363;
    const int cn1 = 961 * (nq1 >> 8) + 31 * ((nq1 >> 4) & 15) + (nq1 & 15) + 3363;

    float acc[8][4];
#pragma unroll
    for (int j = 0; j < 8; j++)
#pragma unroll
        for (int i = 0; i < 4; i++) acc[j][i] = 0.f;
    float wsum0 = 0.f, wsum1 = 0.f;

    // ---- main loop: 16 chunks of 64 keys, 3-stage cp.async ring
    for (int mc = 0; mc < 16; mc++) {
        if (mc < 15) cp_wait1(); else cp_wait0();
        __syncthreads();                    // also orders tab/ks/kc writes
        if (mc + 2 < 16) {
            const float* vsrc = &g_vp[b][g][(mc + 2) << 6][0];
            float* vdst = vsb0 + ((mc + 2) % 3) * VS_BUF;
#pragma unroll
            for (int j = 0; j < 4; j++) {
                int idx = tid + 256 * j;
                int row = idx >> 4, seg = idx & 15;
                cp16(vdst + row * VSP_ + seg * 4, vsrc + row * 64 + seg * 4);
            }
            cp_commit();
        }
        const float* vsb = vsb0 + (mc % 3) * VS_BUF;
        const int m0 = mc << 6;

#pragma unroll
        for (int sub = 0; sub < 8; sub++) {
            const int mk = m0 + (sub << 3);
            float4 k0 = ks4[mk + tg];
            float4 k1 = ks4[mk + tg + 4];
            int c0i = kc[mk + tg], c1i = kc[mk + tg + 4];
            float t00 = tab[cn0 - c0i], t01 = tab[cn0 - c1i];
            float t10 = tab[cn1 - c0i], t11 = tab[cn1 - c1i];

            // bias folded into the innermost FMA of each dot product
            float d00 = fmaf(q0.x, k0.x, fmaf(q0.y, k0.y, fmaf(q0.z, k0.z, fmaf(q0.w, k0.w, t00))));
            float d01 = fmaf(q0.x, k1.x, fmaf(q0.y, k1.y, fmaf(q0.z, k1.z, fmaf(q0.w, k1.w, t01))));
            float d10 = fmaf(q1.x, k0.x, fmaf(q1.y, k0.y, fmaf(q1.z, k0.z, fmaf(q1.w, k0.w, t10))));
            float d11 = fmaf(q1.x, k1.x, fmaf(q1.y, k1.y, fmaf(q1.z, k1.z, fmaf(q1.w, k1.w, t11))));

            float w00 = ex2f(d00);
            float w01 = ex2f(d01);
            float w10 = ex2f(d10);
            float w11 = ex2f(d11);
            wsum0 += w00 + w01;
            wsum1 += w10 + w11;

            unsigned a0 = __float_as_uint(w00), a1 = __float_as_uint(w10);
            unsigned a2 = __float_as_uint(w01), a3 = __float_as_uint(w11);

            // scalar B-frag loads: banks 8*tg + gid -> perfect conflict-free
            const float* vr0 = vsb + ((sub << 3) + tg) * VSP_ + gid;
            const float* vr1 = vr0 + 4 * VSP_;
#pragma unroll
            for (int j = 0; j < 8; j++) {
                unsigned b0 = __float_as_uint(vr0[8 * j]);
                unsigned b1 = __float_as_uint(vr1[8 * j]);
                mma_tf32(acc[j], a0, a1, a2, a3, b0, b1);
            }
        }
    }

    // ---- exact row sums, deferred V affine, epilogue
    wsum0 += __shfl_xor_sync(0xffffffffu, wsum0, 1);
    wsum0 += __shfl_xor_sync(0xffffffffu, wsum0, 2);
    wsum1 += __shfl_xor_sync(0xffffffffu, wsum1, 1);
    wsum1 += __shfl_xor_sync(0xffffffffu, wsum1, 2);
    const float inv0 = 1.f / wsum0, inv1 = 1.f / wsum1;

    float avA[4], avB[4];
#pragma unroll
    for (int dd = 0; dd < 4; dd++) {
        avA[dd] = g_aff[2][b][(g << 2) + dd][0];
        avB[dd] = g_aff[2][b][(g << 2) + dd][1];
    }

    const int t0 = nq0 >> 8, y0 = (nq0 >> 4) & 15, x0 = nq0 & 15;
    const int t1 = nq1 >> 8, y1 = (nq1 >> 4) & 15, x1 = nq1 & 15;
    const size_t ob0 = ((size_t)(b * C_) + (g << 2)) * S_
                     + t0 * 4096 + (y0 << 2) * 64 + (x0 << 2);
    const size_t ob1 = ((size_t)(b * C_) + (g << 2)) * S_
                     + t1 * 4096 + (y1 << 2) * 64 + (x1 << 2);
#pragma unroll
    for (int j = 0; j < 8; j++) {
        int col = 8 * j + 2 * tg;
        int dd = col >> 4, p = col & 15;
        int sy = p >> 2, sx = p & 3;
        size_t off = (size_t)dd * S_ + sy * 64 + sx;
        *(float2*)&out[ob0 + off] = make_float2(
            fmaf(acc[j][0] * inv0, avA[dd], avB[dd]),
            fmaf(acc[j][1] * inv0, avA[dd], avB[dd]));
        *(float2*)&out[ob1 + off] = make_float2(
            fmaf(acc[j][2] * inv1, avA[dd], avB[dd]),
            fmaf(acc[j][3] * inv1, avA[dd], avB[dd]));
    }
}

// ================= launch ==================================================
extern "C" void kernel_launch(void* const* d_in, const int* in_sizes, int n_in,
                              void* d_out, int out_size) {
    const float* x   = (const float*)d_in[0];
    const float* Wq  = (const float*)d_in[1];
    const float* Wk  = (const float*)d_in[2];
    const float* Wv  = (const float*)d_in[3];
    const float* gqg = (const float*)d_in[4];
    const float* gqb = (const float*)d_in[5];
    const float* gkg = (const float*)d_in[6];
    const float* gkb = (const float*)d_in[7];
    const float* gvg = (const float*)d_in[8];
    const float* gvb = (const float*)d_in[9];
    const float* rel_table = (const float*)d_in[10];
    // d_in[11] = rel_index: unused (computed analytically in-kernel)
    float* out = (float*)d_out;

    cudaFuncSetAttribute(proj_kernel, cudaFuncAttributeMaxDynamicSharedMemorySize,
                         PROJ_SMEM_BYTES);
    cudaFuncSetAttribute(attn_kernel, cudaFuncAttributeMaxDynamicSharedMemorySize,
                         ATTN_SMEM_BYTES);

    zero_kernel<<<512, 256>>>();
    split_w_kernel<<<96, 256>>>(Wq, Wk, Wv);
    split_x_kernel<<<2048, 256>>>(x);
    proj_kernel<<<dim3(256, 2, 3), 256, PROJ_SMEM_BYTES>>>();
    finalize_stats<<<1, 192>>>(gqg, gqb, gkg, gkb, gvg, gvb);
    attn_kernel<<<dim3(8, 32, 2), 256, ATTN_SMEM_BYTES>>>(rel_table, out);
}

// round 15
// speedup vs baseline: 1.0584x; 1.0584x over previous
#include <cuda_runtime.h>

// Problem constants
#define B_    2
#define C_    128
#define T_    4
#define S_    16384      // T*H*W
#define NH_   32
#define N_    1024       // T*h*w = 4*16*16
#define TABSZ 6727       // (2T-1)*(2h-1)*(2w-1) = 7*31*31
#define EPS_  1e-5f
#define LOG2E_ 1.4426950408889634f

// ---------------- scratch (static device globals; no runtime alloc) -------
__device__ float g_stat[3][B_][32][2];      // groupnorm sum / sumsq partials
__device__ float g_aff[3][B_][C_][2];       // per-channel affine (a, b)
__device__ float g_qp[B_][NH_][N_][4];      // pooled Q raw sums
__device__ float g_kp[B_][NH_][N_][4];      // pooled K raw sums
__device__ float g_vp[B_][NH_][N_][64];     // RAW V, tf32-rounded, vp layout
// bf16 split components (packed pairs along the K/channel dim)
__device__ unsigned g_w0[3][128][64];       // hi comp of W, bf16x2 (c,c+1)
__device__ unsigned g_w1[3][128][64];       // residual comp
__device__ unsigned g_x0[B_][64][S_];       // hi comp of x, bf16x2 (2cp,2cp+1)
__device__ unsigned g_x1[B_][64][S_];       // residual comp

// ---------------- mma / numeric helpers ------------------------------------
__device__ __forceinline__ unsigned tf32r(float f) {
    unsigned u; asm("cvt.rna.tf32.f32 %0, %1;" : "=r"(u) : "f"(f)); return u;
}
__device__ __forceinline__ void mma_tf32(float* d, unsigned a0, unsigned a1,
                                         unsigned a2, unsigned a3,
                                         unsigned b0, unsigned b1) {
    asm("mma.sync.aligned.m16n8k8.row.col.f32.tf32.tf32.f32 "
        "{%0,%1,%2,%3}, {%4,%5,%6,%7}, {%8,%9}, {%0,%1,%2,%3};"
        : "+f"(d[0]), "+f"(d[1]), "+f"(d[2]), "+f"(d[3])
        : "r"(a0), "r"(a1), "r"(a2), "r"(a3), "r"(b0), "r"(b1));
}
__device__ __forceinline__ void mma_bf16(float* d, unsigned a0, unsigned a1,
                                         unsigned a2, unsigned a3,
                                         unsigned b0, unsigned b1) {
    asm("mma.sync.aligned.m16n8k16.row.col.f32.bf16.bf16.f32 "
        "{%0,%1,%2,%3}, {%4,%5,%6,%7}, {%8,%9}, {%0,%1,%2,%3};"
        : "+f"(d[0]), "+f"(d[1]), "+f"(d[2]), "+f"(d[3])
        : "r"(a0), "r"(a1), "r"(a2), "r"(a3), "r"(b0), "r"(b1));
}
// pack two fp32 into bf16x2: low half = lo arg, high half = hi arg
__device__ __forceinline__ unsigned pack_bf16(float lo, float hi) {
    unsigned r;
    asm("cvt.rn.bf16x2.f32 %0, %1, %2;" : "=r"(r) : "f"(hi), "f"(lo));
    return r;
}
__device__ __forceinline__ float ex2f(float x) {
    float y; asm("ex2.approx.ftz.f32 %0, %1;" : "=f"(y) : "f"(x)); return y;
}

// ---------------- cp.async helpers ----------------------------------------
__device__ __forceinline__ void cp16(void* smem, const void* g) {
    unsigned sa = (unsigned)__cvta_generic_to_shared(smem);
    asm volatile("cp.async.cg.shared.global [%0], [%1], 16;" :: "r"(sa), "l"(g));
}
__device__ __forceinline__ void cp_commit() {
    asm volatile("cp.async.commit_group;");
}
__device__ __forceinline__ void cp_wait0() {
    asm volatile("cp.async.wait_group 0;" ::: "memory");
}
__device__ __forceinline__ void cp_wait1() {
    asm volatile("cp.async.wait_group 1;" ::: "memory");
}

// ================= K0: zero accumulators ===================================
__global__ void zero_kernel() {      // <<<512, 256>>>
    int idx = blockIdx.x * 256 + threadIdx.x;       // 0..131071
    float4 z = make_float4(0.f, 0.f, 0.f, 0.f);
    if (idx < 65536) ((float4*)g_qp)[idx] = z;
    else             ((float4*)g_kp)[idx - 65536] = z;
    if (idx < 96)    ((float4*)g_stat)[idx] = z;
}

// ================= K0b: bf16 split of W ====================================
__global__ void split_w_kernel(const float* __restrict__ Wq,
                               const float* __restrict__ Wk,
                               const float* __restrict__ Wv) {  // <<<96,256>>>
    int idx = blockIdx.x * 256 + threadIdx.x;      // 0..24575
    int pr = idx >> 13, rem = idx & 8191;          // 8192 = 128*64
    int o = rem >> 6, cp = rem & 63;
    const float* Wsel = (pr == 0) ? Wq : ((pr == 1) ? Wk : Wv);
    float vlo = Wsel[o * 128 + 2 * cp];
    float vhi = Wsel[o * 128 + 2 * cp + 1];
    unsigned p0 = pack_bf16(vlo, vhi);
    float rlo = vlo - __uint_as_float(p0 << 16);
    float rhi = vhi - __uint_as_float(p0 & 0xFFFF0000u);
    g_w0[pr][o][cp] = p0;
    g_w1[pr][o][cp] = pack_bf16(rlo, rhi);
}

// ================= K0c: bf16 split of x ====================================
__global__ __launch_bounds__(256) void split_x_kernel(
    const float* __restrict__ x) {                 // <<<2048,256>>>
    int idx = blockIdx.x * 256 + threadIdx.x;      // 0..524287
    int s4 = idx & 4095, cp = (idx >> 12) & 63, b = idx >> 18;
    const float* xlo = x + ((size_t)(b * 128 + 2 * cp)) * S_ + (s4 << 2);
    float4 vl = *(const float4*)xlo;
    float4 vh = *(const float4*)(xlo + S_);
    unsigned p0[4], p1[4];
    float l[4] = {vl.x, vl.y, vl.z, vl.w};
    float h[4] = {vh.x, vh.y, vh.z, vh.w};
#pragma unroll
    for (int i = 0; i < 4; i++) {
        p0[i] = pack_bf16(l[i], h[i]);
        float rl = l[i] - __uint_as_float(p0[i] << 16);
        float rh = h[i] - __uint_as_float(p0[i] & 0xFFFF0000u);
        p1[i] = pack_bf16(rl, rh);
    }
    *(uint4*)&g_x0[b][cp][s4 << 2] = make_uint4(p0[0], p0[1], p0[2], p0[3]);
    *(uint4*)&g_x1[b][cp][s4 << 2] = make_uint4(p1[0], p1[1], p1[2], p1[3]);
}

// ================= K1: projections via bf16-split tensor GEMM ==============
// Per CTA: 128 o x 128 s tile (2 hh rows); K=128 in 4 chunks of 32c,
// double-buffered cp.async of packed bf16x2 components.
// Warp = (ow 0..3, sw 0..1): 32 o x 64 s (one hh row each; same patches!).
// w*x ~= w0x0 + w1x0 + w0x1 (error ~2^-16) via m16n8k16 bf16 MMA,
// issued as term sweeps (bx0 reused for two sweeps).
#define XP_   136
#define WSTG  (128 * 36)              // 4608 uints / stage
#define XSTG  (2 * 16 * XP_)          // 4352 uints / stage
#define XCOMP (16 * XP_)              // 2176: residual component offset
#define SB_OFF (2 * WSTG + 2 * XSTG)  // 17920
#define PROJ_SMEM_FLOATS (SB_OFF + 512)
#define PROJ_SMEM_BYTES  (PROJ_SMEM_FLOATS * 4)

__global__ __launch_bounds__(256) void proj_kernel() {
    extern __shared__ float sm[];
    unsigned* Ws = (unsigned*)sm;
    unsigned* Xs = (unsigned*)sm + 2 * WSTG;
    float* sbuf  = sm + SB_OFF;

    const int pr  = blockIdx.z;
    const int b   = blockIdx.y;
    const int s_t = blockIdx.x << 7;               // 128-s tile
    const int tid = threadIdx.x;

    auto issue = [&](int kc, int st) {
        unsigned* wd = Ws + st * WSTG;
        unsigned* xd = Xs + st * XSTG;
#pragma unroll
        for (int j = 0; j < 4; j++) {          // W: 4096 uints = 1024 cp16
            int e = tid + 256 * j;
            int o = e >> 3, grp = e & 7;
            int comp = grp >> 2, seg = grp & 3;
            const unsigned* src = comp ? &g_w1[pr][o][kc * 16 + seg * 4]
                                       : &g_w0[pr][o][kc * 16 + seg * 4];
            cp16(wd + o * 36 + comp * 16 + seg * 4, src);
        }
#pragma unroll
        for (int j = 0; j < 4; j++) {          // X: 4096 uints = 1024 cp16
            int e = tid + 256 * j;
            int comp = e >> 9, r = e & 511;
            int cp = r >> 5, seg = r & 31;
            const unsigned* src = comp ? &g_x1[b][kc * 16 + cp][s_t + seg * 4]
                                       : &g_x0[b][kc * 16 + cp][s_t + seg * 4];
            cp16(xd + comp * XCOMP + cp * XP_ + seg * 4, src);
        }
        cp_commit();
    };

    const int warp = tid >> 5, lane = tid & 31;
    const int gid = lane >> 2, tg = lane & 3;
    const int ow = warp >> 1, sw = warp & 1;
    const int o0 = ow << 5;                        // 32 o per warp
    const int sbase = sw << 6;                     // 64 s per warp (one hh row)

    float acc[2][8][4];
#pragma unroll
    for (int mb = 0; mb < 2; mb++)
#pragma unroll
        for (int nb = 0; nb < 8; nb++)
#pragma unroll
            for (int i = 0; i < 4; i++) acc[mb][nb][i] = 0.f;

    issue(0, 0);
    for (int kc = 0; kc < 4; kc++) {
        cp_wait0();
        __syncthreads();
        if (kc < 3) issue(kc + 1, (kc + 1) & 1);
        const unsigned* Wb = Ws + (kc & 1) * WSTG;
        const unsigned* Xb = Xs + (kc & 1) * XSTG;

#pragma unroll
        for (int ks2 = 0; ks2 < 2; ks2++) {
            const int kb = ks2 << 3;
            // A frags for both mb tiles, both components
            unsigned A0[2][4], A1[2][4];
#pragma unroll
            for (int mb = 0; mb < 2; mb++) {
                const unsigned* w0p = Wb + (o0 + mb * 16 + gid) * 36 + kb + tg;
                const unsigned* w1p = w0p + 16;
                A0[mb][0] = w0p[0];  A0[mb][1] = w0p[8 * 36];
                A0[mb][2] = w0p[4];  A0[mb][3] = w0p[8 * 36 + 4];
                A1[mb][0] = w1p[0];  A1[mb][1] = w1p[8 * 36];
                A1[mb][2] = w1p[4];  A1[mb][3] = w1p[8 * 36 + 4];
            }
            // hi X component: used by two term-sweeps (w0x0, w1x0)
            unsigned bx[8][2];
#pragma unroll
            for (int nb = 0; nb < 8; nb++) {
                const unsigned* xc = Xb + (kb + tg) * XP_ + sbase + nb * 8 + gid;
                bx[nb][0] = xc[0];
                bx[nb][1] = xc[4 * XP_];
            }
#pragma unroll
            for (int mb = 0; mb < 2; mb++)
#pragma unroll
                for (int nb = 0; nb < 8; nb++)
                    mma_bf16(acc[mb][nb], A0[mb][0], A0[mb][1], A0[mb][2], A0[mb][3],
                             bx[nb][0], bx[nb][1]);
#pragma unroll
            for (int mb = 0; mb < 2; mb++)
#pragma unroll
                for (int nb = 0; nb < 8; nb++)
                    mma_bf16(acc[mb][nb], A1[mb][0], A1[mb][1], A1[mb][2], A1[mb][3],
                             bx[nb][0], bx[nb][1]);
            // residual X component: one sweep (w0x1)
#pragma unroll
            for (int nb = 0; nb < 8; nb++) {
                const unsigned* xc = Xb + XCOMP + (kb + tg) * XP_ + sbase + nb * 8 + gid;
                bx[nb][0] = xc[0];
                bx[nb][1] = xc[4 * XP_];
            }
#pragma unroll
            for (int mb = 0; mb < 2; mb++)
#pragma unroll
                for (int nb = 0; nb < 8; nb++)
                    mma_bf16(acc[mb][nb], A0[mb][0], A0[mb][1], A0[mb][2], A0[mb][3],
                             bx[nb][0], bx[nb][1]);
        }
        __syncthreads();
    }

    // ---- epilogue coordinates (tile spans hh0, hh0+1; hh0 even -> same y)
    const int t   = s_t >> 12;
    const int hh0 = (s_t >> 6) & 63;
    const int y   = hh0 >> 2;
    const int nbase = t * 256 + (y << 4);

    if (pr < 2) {
        float* dstp = (pr == 0) ? &g_qp[0][0][0][0] : &g_kp[0][0][0][0];
#pragma unroll
        for (int mb = 0; mb < 2; mb++) {
            const int cA = o0 + mb * 16 + gid, cB = cA + 8;
#pragma unroll
            for (int nb = 0; nb < 8; nb++) {
                float sA = acc[mb][nb][0] + acc[mb][nb][1];
                float sB = acc[mb][nb][2] + acc[mb][nb][3];
                sA += __shfl_xor_sync(0xffffffffu, sA, 1);
                sB += __shfl_xor_sync(0xffffffffu, sB, 1);
                if ((tg & 1) == 0) {
                    int n = nbase + (nb << 1) + (tg >> 1);
                    atomicAdd(dstp + (((size_t)(b * 32 + (cA >> 2)) * 1024 + n) << 2)
                                   + (cA & 3), sA);
                    atomicAdd(dstp + (((size_t)(b * 32 + (cB >> 2)) * 1024 + n) << 2)
                                   + (cB & 3), sB);
                }
            }
        }
    } else {
        float* Zs = sm;                      // 128 x 136 = 17408 < SB_OFF
#pragma unroll
        for (int mb = 0; mb < 2; mb++) {
            const int r = o0 + mb * 16 + gid;
#pragma unroll
            for (int nb = 0; nb < 8; nb++) {
                int col = sbase + nb * 8 + (tg << 1);
                *(float2*)&Zs[r * XP_ + col]       = make_float2(acc[mb][nb][0], acc[mb][nb][1]);
                *(float2*)&Zs[(r + 8) * XP_ + col] = make_float2(acc[mb][nb][2], acc[mb][nb][3]);
            }
        }
    }

    // ---- fused GroupNorm partial stats
#pragma unroll
    for (int mb = 0; mb < 2; mb++)
#pragma unroll
        for (int hi = 0; hi < 2; hi++) {
            float s = 0.f, s2 = 0.f;
#pragma unroll
            for (int nb = 0; nb < 8; nb++) {
                float v0 = acc[mb][nb][hi * 2 + 0];
                float v1 = acc[mb][nb][hi * 2 + 1];
                s += v0 + v1;
                s2 = fmaf(v0, v0, s2); s2 = fmaf(v1, v1, s2);
            }
            s  += __shfl_xor_sync(0xffffffffu, s, 1);
            s  += __shfl_xor_sync(0xffffffffu, s, 2);
            s2 += __shfl_xor_sync(0xffffffffu, s2, 1);
            s2 += __shfl_xor_sync(0xffffffffu, s2, 2);
            if (tg == 0) {
                int idx = (((warp << 3) | gid) << 3) | (mb << 2) | (hi << 1);
                sbuf[idx]     = s;
                sbuf[idx + 1] = s2;
            }
        }
    __syncthreads();

    if (pr == 2) {
        // scatter raw tf32 v into vp layout: 4096 float4 over 256 threads
        const float* Zs = sm;
#pragma unroll
        for (int j = 0; j < 16; j++) {
            int e = tid + (j << 8);
            int c = e >> 5, xs4 = e & 31;
            int xs = xs4 << 2;
            float4 v = *(const float4*)&Zs[c * XP_ + xs];
            float4 r = make_float4(
                __uint_as_float(tf32r(v.x)), __uint_as_float(tf32r(v.y)),
                __uint_as_float(tf32r(v.z)), __uint_as_float(tf32r(v.w)));
            int hh = hh0 + (xs >> 6);
            int sy = hh & 3;
            int xq = (xs & 63) >> 2;
            *(float4*)&g_vp[b][c >> 2][nbase + xq][((c & 3) << 4) + (sy << 2)] = r;
        }
    }
    if (tid < 64) {
        int grp = tid >> 1, v = tid & 1;
        float tot = 0.f;
#pragma unroll
        for (int ci = 0; ci < 4; ci++) {
            int ch = (grp << 2) + ci;
            int cow = ch >> 5, r = ch & 31;
            int cmb = r >> 4, chi = (r >> 3) & 1, cgid = r & 7;
#pragma unroll
            for (int csw = 0; csw < 2; csw++) {
                int w2 = (cow << 1) | csw;
                tot += sbuf[(((w2 << 3) | cgid) << 3) | (cmb << 2) | (chi << 1) | v];
            }
        }
        atomicAdd(&g_stat[pr][b][grp][v], tot);
    }
}

// ================= K2: finalize stats -> per-channel affine ================
__global__ void finalize_stats(
    const float* __restrict__ gqg, const float* __restrict__ gqb,
    const float* __restrict__ gkg, const float* __restrict__ gkb,
    const float* __restrict__ gvg, const float* __restrict__ gvb) {   // <<<1,192>>>
    int i = threadIdx.x;
    int pr = i >> 6, r = i & 63, b = r >> 5, grp = r & 31;
    float s  = g_stat[pr][b][grp][0];
    float s2 = g_stat[pr][b][grp][1];
    float mean = s * (1.f / 65536.f);
    float var  = s2 * (1.f / 65536.f) - mean * mean;
    float rstd = rsqrtf(var + EPS_);
    const float* ga = (pr == 0) ? gqg : ((pr == 1) ? gkg : gvg);
    const float* be = (pr == 0) ? gqb : ((pr == 1) ? gkb : gvb);
#pragma unroll
    for (int d = 0; d < 4; d++) {
        int c = (grp << 2) + d;
        float a = rstd * ga[c];
        g_aff[pr][b][c][0] = a;
        g_aff[pr][b][c][1] = be[c] - mean * a;
    }
}

// ================= K3: fused tensor-core patch attention ===================
// Round-14 structure: GN-normalized q/k keep logits small -> no bound needed;
// w = ex2(q.k*HS + tab) with tab folded into the dot's FMA chain.
#define VSP_    72
#define VS_BUF  (64 * VSP_)                 // 4608 floats per stage
#define SM_TAB  0
#define SM_K    6728                        // 1024 float4
#define SM_KC   (SM_K + 4096)               // 1024 ints
#define SM_VS   (SM_KC + 1024)              // 3 * 4608
#define ATTN_SMEM_FLOATS (SM_VS + 3 * VS_BUF)
#define ATTN_SMEM_BYTES (ATTN_SMEM_FLOATS * 4)

__global__ __launch_bounds__(256, 2) void attn_kernel(
    const float* __restrict__ rel_table, float* __restrict__ out) {
    extern __shared__ float sm[];
    float*  tab  = sm + SM_TAB;
    float4* ks4  = (float4*)(sm + SM_K);
    int*    kc   = (int*)(sm + SM_KC);
    float*  vsb0 = sm + SM_VS;

    const int b = blockIdx.z, g = blockIdx.y;
    const int n0 = blockIdx.x << 7;
    const int tid = threadIdx.x;

    // ---- kick off V chunks 0 and 1 immediately
#pragma unroll
    for (int st = 0; st < 2; st++) {
        const float* vsrc = &g_vp[b][g][st << 6][0];
        float* vdst = vsb0 + st * VS_BUF;
#pragma unroll
        for (int j = 0; j < 4; j++) {
            int idx = tid + 256 * j;
            int row = idx >> 4, seg = idx & 15;
            cp16(vdst + row * VSP_ + seg * 4, vsrc + row * 64 + seg * 4);
        }
        cp_commit();
    }

    // ---- load bias table (scaled by log2e) and normalized K + kc
    for (int i = tid; i < TABSZ; i += 256)
        tab[i] = rel_table[g * TABSZ + i] * LOG2E_;
    const float* afk = &g_aff[1][b][g << 2][0];     // [a0,b0,a1,b1,a2,b2,a3,b3]
    float4 afk0 = *(const float4*)afk;
    float4 afk1 = *(const float4*)(afk + 4);
    for (int i = tid; i < 1024; i += 256) {
        float4 kr = *(const float4*)&g_kp[b][g][i][0];
        float4 kk;
        kk.x = fmaf(kr.x * 0.0625f, afk0.x, afk0.y);
        kk.y = fmaf(kr.y * 0.0625f, afk0.z, afk0.w);
        kk.z = fmaf(kr.z * 0.0625f, afk1.x, afk1.y);
        kk.w = fmaf(kr.w * 0.0625f, afk1.z, afk1.w);
        ks4[i] = kk;
        kc[i]  = 961 * (i >> 8) + 31 * ((i >> 4) & 15) + (i & 15);
    }

    // ---- per-thread identity; q: normalize then scale to log2 domain
    const int warp = tid >> 5, lane = tid & 31;
    const int gid = lane >> 2, tg = lane & 3;
    const int r0 = (warp << 4) + gid;
    const int nq0 = n0 + r0, nq1 = nq0 + 8;
    const float* afq = &g_aff[0][b][g << 2][0];
    float4 afq0 = *(const float4*)afq;
    float4 afq1 = *(const float4*)(afq + 4);
    const float HS = 0.5f * LOG2E_;
    float4 qr0 = *(const float4*)&g_qp[b][g][nq0][0];
    float4 qr1 = *(const float4*)&g_qp[b][g][nq1][0];
    float4 q0, q1;
    q0.x = fmaf(qr0.x * 0.0625f, afq0.x, afq0.y) * HS;
    q0.y = fmaf(qr0.y * 0.0625f, afq0.z, afq0.w) * HS;
    q0.z = fmaf(qr0.z * 0.0625f, afq1.x, afq1.y) * HS;
    q0.w = fmaf(qr0.w * 0.0625f, afq1.z, afq1.w) * HS;
    q1.x = fmaf(qr1.x * 0.0625f, afq0.x, afq0.y) * HS;
    q1.y = fmaf(qr1.y * 0.0625f, afq0.z, afq0.w) * HS;
    q1.z = fmaf(qr1.z * 0.0625f, afq1.x, afq1.y) * HS;
    q1.w = fmaf(qr1.w * 0.0625f, afq1.z, afq1.w) * HS;
    const int cn0 = 961 * (nq0 >> 8) + 31 * ((nq0 >> 4) & 15) + (nq0 & 15) + 3363;
    const int cn1 = 961 * (nq1 >> 8) + 31 * ((nq1 >> 4) & 15) + (nq1 & 15) + 3363;

    float acc[8][4];
#pragma unroll
    for (int j = 0; j < 8; j++)
#pragma unroll
        for (int i = 0; i < 4; i++) acc[j][i] = 0.f;
    float wsum0 = 0.f, wsum1 = 0.f;

    // ---- main loop: 16 chunks of 64 keys, 3-stage cp.async ring
    for (int mc = 0; mc < 16; mc++) {
        if (mc < 15) cp_wait1(); else cp_wait0();
        __syncthreads();                    // also orders tab/ks/kc writes
        if (mc + 2 < 16) {
            const float* vsrc = &g_vp[b][g][(mc + 2) << 6][0];
            float* vdst = vsb0 + ((mc + 2) % 3) * VS_BUF;
#pragma unroll
            for (int j = 0; j < 4; j++) {
                int idx = tid + 256 * j;
                int row = idx >> 4, seg = idx & 15;
                cp16(vdst + row * VSP_ + seg * 4, vsrc + row * 64 + seg * 4);
            }
            cp_commit();
        }
        const float* vsb = vsb0 + (mc % 3) * VS_BUF;
        const int m0 = mc << 6;

#pragma unroll
        for (int sub = 0; sub < 8; sub++) {
            const int mk = m0 + (sub << 3);
            float4 k0 = ks4[mk + tg];
            float4 k1 = ks4[mk + tg + 4];
            int c0i = kc[mk + tg], c1i = kc[mk + tg + 4];
            float t00 = tab[cn0 - c0i], t01 = tab[cn0 - c1i];
            float t10 = tab[cn1 - c0i], t11 = tab[cn1 - c1i];

            // bias folded into the innermost FMA of each dot product
            float d00 = fmaf(q0.x, k0.x, fmaf(q0.y, k0.y, fmaf(q0.z, k0.z, fmaf(q0.w, k0.w, t00))));
            float d01 = fmaf(q0.x, k1.x, fmaf(q0.y, k1.y, fmaf(q0.z, k1.z, fmaf(q0.w, k1.w, t01))));
            float d10 = fmaf(q1.x, k0.x, fmaf(q1.y, k0.y, fmaf(q1.z, k0.z, fmaf(q1.w, k0.w, t10))));
            float d11 = fmaf(q1.x, k1.x, fmaf(q1.y, k1.y, fmaf(q1.z, k1.z, fmaf(q1.w, k1.w, t11))));

            float w00 = ex2f(d00);
            float w01 = ex2f(d01);
            float w10 = ex2f(d10);
            float w11 = ex2f(d11);
            wsum0 += w00 + w01;
            wsum1 += w10 + w11;

            unsigned a0 = __float_as_uint(w00), a1 = __float_as_uint(w10);
            unsigned a2 = __float_as_uint(w01), a3 = __float_as_uint(w11);

            // scalar B-frag loads: banks 8*tg + gid -> perfect conflict-free
            const float* vr0 = vsb + ((sub << 3) + tg) * VSP_ + gid;
            const float* vr1 = vr0 + 4 * VSP_;
#pragma unroll
            for (int j = 0; j < 8; j++) {
                unsigned b0 = __float_as_uint(vr0[8 * j]);
                unsigned b1 = __float_as_uint(vr1[8 * j]);
                mma_tf32(acc[j], a0, a1, a2, a3, b0, b1);
            }
        }
    }

    // ---- exact row sums, deferred V affine, epilogue
    wsum0 += __shfl_xor_sync(0xffffffffu, wsum0, 1);
    wsum0 += __shfl_xor_sync(0xffffffffu, wsum0, 2);
    wsum1 += __shfl_xor_sync(0xffffffffu, wsum1, 1);
    wsum1 += __shfl_xor_sync(0xffffffffu, wsum1, 2);
    const float inv0 = 1.f / wsum0, inv1 = 1.f / wsum1;

    float avA[4], avB[4];
#pragma unroll
    for (int dd = 0; dd < 4; dd++) {
        avA[dd] = g_aff[2][b][(g << 2) + dd][0];
        avB[dd] = g_aff[2][b][(g << 2) + dd][1];
    }

    const int t0 = nq0 >> 8, y0 = (nq0 >> 4) & 15, x0 = nq0 & 15;
    const int t1 = nq1 >> 8, y1 = (nq1 >> 4) & 15, x1 = nq1 & 15;
    const size_t ob0 = ((size_t)(b * C_) + (g << 2)) * S_
                     + t0 * 4096 + (y0 << 2) * 64 + (x0 << 2);
    const size_t ob1 = ((size_t)(b * C_) + (g << 2)) * S_
                     + t1 * 4096 + (y1 << 2) * 64 + (x1 << 2);
#pragma unroll
    for (int j = 0; j < 8; j++) {
        int col = 8 * j + 2 * tg;
        int dd = col >> 4, p = col & 15;
        int sy = p >> 2, sx = p & 3;
        size_t off = (size_t)dd * S_ + sy * 64 + sx;
        *(float2*)&out[ob0 + off] = make_float2(
            fmaf(acc[j][0] * inv0, avA[dd], avB[dd]),
            fmaf(acc[j][1] * inv0, avA[dd], avB[dd]));
        *(float2*)&out[ob1 + off] = make_float2(
            fmaf(acc[j][2] * inv1, avA[dd], avB[dd]),
            fmaf(acc[j][3] * inv1, avA[dd], avB[dd]));
    }
}

// ================= launch ==================================================
extern "C" void kernel_launch(void* const* d_in, const int* in_sizes, int n_in,
                              void* d_out, int out_size) {
    const float* x   = (const float*)d_in[0];
    const float* Wq  = (const float*)d_in[1];
    const float* Wk  = (const float*)d_in[2];
    const float* Wv  = (const float*)d_in[3];
    const float* gqg = (const float*)d_in[4];
    const float* gqb = (const float*)d_in[5];
    const float* gkg = (const float*)d_in[6];
    const float* gkb = (const float*)d_in[7];
    const float* gvg = (const float*)d_in[8];
    const float* gvb = (const float*)d_in[9];
    const float* rel_table = (const float*)d_in[10];
    // d_in[11] = rel_index: unused (computed analytically in-kernel)
    float* out = (float*)d_out;

    cudaFuncSetAttribute(proj_kernel, cudaFuncAttributeMaxDynamicSharedMemorySize,
                         PROJ_SMEM_BYTES);
    cudaFuncSetAttribute(attn_kernel, cudaFuncAttributeMaxDynamicSharedMemorySize,
                         ATTN_SMEM_BYTES);

    zero_kernel<<<512, 256>>>();
    split_w_kernel<<<96, 256>>>(Wq, Wk, Wv);
    split_x_kernel<<<2048, 256>>>(x);
    proj_kernel<<<dim3(128, 2, 3), 256, PROJ_SMEM_BYTES>>>();
    finalize_stats<<<1, 192>>>(gqg, gqb, gkg, gkb, gvg, gvb);
    attn_kernel<<<dim3(8, 32, 2), 256, ATTN_SMEM_BYTES>>>(rel_table, out);
}

// round 17
// speedup vs baseline: 1.0954x; 1.0349x over previous
#include <cuda_runtime.h>

// Problem constants
#define B_    2
#define C_    128
#define T_    4
#define S_    16384      // T*H*W
#define NH_   32
#define N_    1024       // T*h*w = 4*16*16
#define TABSZ 6727       // (2T-1)*(2h-1)*(2w-1) = 7*31*31
#define EPS_  1e-5f
#define LOG2E_ 1.4426950408889634f

// ---------------- scratch (static device globals; no runtime alloc) -------
__device__ float g_stat[3][B_][32][2];      // groupnorm sum / sumsq partials
__device__ float g_aff[3][B_][C_][2];       // per-channel affine (a, b)
__device__ float g_qp[B_][NH_][N_][4];      // pooled Q raw sums
__device__ float g_kp[B_][NH_][N_][4];      // pooled K raw sums
__device__ float g_vp[B_][NH_][N_][64];     // RAW V, tf32-rounded, vp layout
// bf16 split components (packed pairs along the K/channel dim)
__device__ unsigned g_w0[3][128][64];       // hi comp of W, bf16x2 (c,c+1)
__device__ unsigned g_w1[3][128][64];       // residual comp
__device__ unsigned g_x0[B_][64][S_];       // hi comp of x, bf16x2 (2cp,2cp+1)
__device__ unsigned g_x1[B_][64][S_];       // residual comp

// ---------------- mma / numeric helpers ------------------------------------
__device__ __forceinline__ unsigned tf32r(float f) {
    unsigned u; asm("cvt.rna.tf32.f32 %0, %1;" : "=r"(u) : "f"(f)); return u;
}
__device__ __forceinline__ void mma_tf32(float* d, unsigned a0, unsigned a1,
                                         unsigned a2, unsigned a3,
                                         unsigned b0, unsigned b1) {
    asm("mma.sync.aligned.m16n8k8.row.col.f32.tf32.tf32.f32 "
        "{%0,%1,%2,%3}, {%4,%5,%6,%7}, {%8,%9}, {%0,%1,%2,%3};"
        : "+f"(d[0]), "+f"(d[1]), "+f"(d[2]), "+f"(d[3])
        : "r"(a0), "r"(a1), "r"(a2), "r"(a3), "r"(b0), "r"(b1));
}
__device__ __forceinline__ void mma_bf16(float* d, unsigned a0, unsigned a1,
                                         unsigned a2, unsigned a3,
                                         unsigned b0, unsigned b1) {
    asm("mma.sync.aligned.m16n8k16.row.col.f32.bf16.bf16.f32 "
        "{%0,%1,%2,%3}, {%4,%5,%6,%7}, {%8,%9}, {%0,%1,%2,%3};"
        : "+f"(d[0]), "+f"(d[1]), "+f"(d[2]), "+f"(d[3])
        : "r"(a0), "r"(a1), "r"(a2), "r"(a3), "r"(b0), "r"(b1));
}
// pack two fp32 into bf16x2: low half = lo arg, high half = hi arg
__device__ __forceinline__ unsigned pack_bf16(float lo, float hi) {
    unsigned r;
    asm("cvt.rn.bf16x2.f32 %0, %1, %2;" : "=r"(r) : "f"(hi), "f"(lo));
    return r;
}
__device__ __forceinline__ float ex2f(float x) {
    float y; asm("ex2.approx.ftz.f32 %0, %1;" : "=f"(y) : "f"(x)); return y;
}

// ---------------- cp.async helpers ----------------------------------------
__device__ __forceinline__ void cp16(void* smem, const void* g) {
    unsigned sa = (unsigned)__cvta_generic_to_shared(smem);
    asm volatile("cp.async.cg.shared.global [%0], [%1], 16;" :: "r"(sa), "l"(g));
}
__device__ __forceinline__ void cp_commit() {
    asm volatile("cp.async.commit_group;");
}
__device__ __forceinline__ void cp_wait0() {
    asm volatile("cp.async.wait_group 0;" ::: "memory");
}
__device__ __forceinline__ void cp_wait1() {
    asm volatile("cp.async.wait_group 1;" ::: "memory");
}

// ================= K0: zero accumulators ===================================
__global__ void zero_kernel() {      // <<<512, 256>>>
    int idx = blockIdx.x * 256 + threadIdx.x;       // 0..131071
    float4 z = make_float4(0.f, 0.f, 0.f, 0.f);
    if (idx < 65536) ((float4*)g_qp)[idx] = z;
    else             ((float4*)g_kp)[idx - 65536] = z;
    if (idx < 96)    ((float4*)g_stat)[idx] = z;
}

// ================= K0b: bf16 split of W ====================================
__global__ void split_w_kernel(const float* __restrict__ Wq,
                               const float* __restrict__ Wk,
                               const float* __restrict__ Wv) {  // <<<96,256>>>
    int idx = blockIdx.x * 256 + threadIdx.x;      // 0..24575
    int pr = idx >> 13, rem = idx & 8191;          // 8192 = 128*64
    int o = rem >> 6, cp = rem & 63;
    const float* Wsel = (pr == 0) ? Wq : ((pr == 1) ? Wk : Wv);
    float vlo = Wsel[o * 128 + 2 * cp];
    float vhi = Wsel[o * 128 + 2 * cp + 1];
    unsigned p0 = pack_bf16(vlo, vhi);
    float rlo = vlo - __uint_as_float(p0 << 16);
    float rhi = vhi - __uint_as_float(p0 & 0xFFFF0000u);
    g_w0[pr][o][cp] = p0;
    g_w1[pr][o][cp] = pack_bf16(rlo, rhi);
}

// ================= K0c: bf16 split of x ====================================
__global__ __launch_bounds__(256) void split_x_kernel(
    const float* __restrict__ x) {                 // <<<2048,256>>>
    int idx = blockIdx.x * 256 + threadIdx.x;      // 0..524287
    int s4 = idx & 4095, cp = (idx >> 12) & 63, b = idx >> 18;
    const float* xlo = x + ((size_t)(b * 128 + 2 * cp)) * S_ + (s4 << 2);
    float4 vl = *(const float4*)xlo;
    float4 vh = *(const float4*)(xlo + S_);
    unsigned p0[4], p1[4];
    float l[4] = {vl.x, vl.y, vl.z, vl.w};
    float h[4] = {vh.x, vh.y, vh.z, vh.w};
#pragma unroll
    for (int i = 0; i < 4; i++) {
        p0[i] = pack_bf16(l[i], h[i]);
        float rl = l[i] - __uint_as_float(p0[i] << 16);
        float rh = h[i] - __uint_as_float(p0[i] & 0xFFFF0000u);
        p1[i] = pack_bf16(rl, rh);
    }
    *(uint4*)&g_x0[b][cp][s4 << 2] = make_uint4(p0[0], p0[1], p0[2], p0[3]);
    *(uint4*)&g_x1[b][cp][s4 << 2] = make_uint4(p1[0], p1[1], p1[2], p1[3]);
}

// ================= K1: projections via bf16-split tensor GEMM ==============
// Per CTA: 128 o x 128 s tile (2 hh rows); K=128 in 4 chunks of 32c,
// double-buffered cp.async of packed bf16x2 components.
// Warp = (ow 0..3, sw 0..1): 32 o x 64 s (one hh row each; same patches!).
// w*x ~= w0x0 + w1x0 + w0x1 (error ~2^-16) via m16n8k16 bf16 MMA.
#define XP_   136
#define WSTG  (128 * 36)              // 4608 uints / stage
#define XSTG  (2 * 16 * XP_)          // 4352 uints / stage
#define XCOMP (16 * XP_)              // 2176: residual component offset
#define SB_OFF (2 * WSTG + 2 * XSTG)  // 17920
#define PROJ_SMEM_FLOATS (SB_OFF + 512)
#define PROJ_SMEM_BYTES  (PROJ_SMEM_FLOATS * 4)

__global__ __launch_bounds__(256) void proj_kernel() {
    extern __shared__ float sm[];
    unsigned* Ws = (unsigned*)sm;
    unsigned* Xs = (unsigned*)sm + 2 * WSTG;
    float* sbuf  = sm + SB_OFF;

    const int pr  = blockIdx.z;
    const int b   = blockIdx.y;
    const int s_t = blockIdx.x << 7;               // 128-s tile
    const int tid = threadIdx.x;

    auto issue = [&](int kc, int st) {
        unsigned* wd = Ws + st * WSTG;
        unsigned* xd = Xs + st * XSTG;
#pragma unroll
        for (int j = 0; j < 4; j++) {          // W: 4096 uints = 1024 cp16
            int e = tid + 256 * j;
            int o = e >> 3, grp = e & 7;
            int comp = grp >> 2, seg = grp & 3;
            const unsigned* src = comp ? &g_w1[pr][o][kc * 16 + seg * 4]
                                       : &g_w0[pr][o][kc * 16 + seg * 4];
            cp16(wd + o * 36 + comp * 16 + seg * 4, src);
        }
#pragma unroll
        for (int j = 0; j < 4; j++) {          // X: 4096 uints = 1024 cp16
            int e = tid + 256 * j;
            int comp = e >> 9, r = e & 511;
            int cp = r >> 5, seg = r & 31;
            const unsigned* src = comp ? &g_x1[b][kc * 16 + cp][s_t + seg * 4]
                                       : &g_x0[b][kc * 16 + cp][s_t + seg * 4];
            cp16(xd + comp * XCOMP + cp * XP_ + seg * 4, src);
        }
        cp_commit();
    };

    const int warp = tid >> 5, lane = tid & 31;
    const int gid = lane >> 2, tg = lane & 3;
    const int ow = warp >> 1, sw = warp & 1;
    const int o0 = ow << 5;                        // 32 o per warp
    const int sbase = sw << 6;                     // 64 s per warp (one hh row)

    float acc[2][8][4];
#pragma unroll
    for (int mb = 0; mb < 2; mb++)
#pragma unroll
        for (int nb = 0; nb < 8; nb++)
#pragma unroll
            for (int i = 0; i < 4; i++) acc[mb][nb][i] = 0.f;

    issue(0, 0);
    for (int kc = 0; kc < 4; kc++) {
        cp_wait0();
        __syncthreads();
        if (kc < 3) issue(kc + 1, (kc + 1) & 1);
        const unsigned* Wb = Ws + (kc & 1) * WSTG;
        const unsigned* Xb = Xs + (kc & 1) * XSTG;

#pragma unroll
        for (int ks2 = 0; ks2 < 2; ks2++) {
            const int kb = ks2 << 3;
            unsigned A0[2][4], A1[2][4];
#pragma unroll
            for (int mb = 0; mb < 2; mb++) {
                const unsigned* w0p = Wb + (o0 + mb * 16 + gid) * 36 + kb + tg;
                const unsigned* w1p = w0p + 16;
                A0[mb][0] = w0p[0];  A0[mb][1] = w0p[8 * 36];
                A0[mb][2] = w0p[4];  A0[mb][3] = w0p[8 * 36 + 4];
                A1[mb][0] = w1p[0];  A1[mb][1] = w1p[8 * 36];
                A1[mb][2] = w1p[4];  A1[mb][3] = w1p[8 * 36 + 4];
            }
            unsigned bx[8][2];
#pragma unroll
            for (int nb = 0; nb < 8; nb++) {
                const unsigned* xc = Xb + (kb + tg) * XP_ + sbase + nb * 8 + gid;
                bx[nb][0] = xc[0];
                bx[nb][1] = xc[4 * XP_];
            }
#pragma unroll
            for (int mb = 0; mb < 2; mb++)
#pragma unroll
                for (int nb = 0; nb < 8; nb++)
                    mma_bf16(acc[mb][nb], A0[mb][0], A0[mb][1], A0[mb][2], A0[mb][3],
                             bx[nb][0], bx[nb][1]);
#pragma unroll
            for (int mb = 0; mb < 2; mb++)
#pragma unroll
                for (int nb = 0; nb < 8; nb++)
                    mma_bf16(acc[mb][nb], A1[mb][0], A1[mb][1], A1[mb][2], A1[mb][3],
                             bx[nb][0], bx[nb][1]);
#pragma unroll
            for (int nb = 0; nb < 8; nb++) {
                const unsigned* xc = Xb + XCOMP + (kb + tg) * XP_ + sbase + nb * 8 + gid;
                bx[nb][0] = xc[0];
                bx[nb][1] = xc[4 * XP_];
            }
#pragma unroll
            for (int mb = 0; mb < 2; mb++)
#pragma unroll
                for (int nb = 0; nb < 8; nb++)
                    mma_bf16(acc[mb][nb], A0[mb][0], A0[mb][1], A0[mb][2], A0[mb][3],
                             bx[nb][0], bx[nb][1]);
        }
        __syncthreads();
    }

    // ---- epilogue coordinates (tile spans hh0, hh0+1; hh0 even -> same y)
    const int t   = s_t >> 12;
    const int hh0 = (s_t >> 6) & 63;
    const int y   = hh0 >> 2;
    const int nbase = t * 256 + (y << 4);

    if (pr < 2) {
        float* dstp = (pr == 0) ? &g_qp[0][0][0][0] : &g_kp[0][0][0][0];
#pragma unroll
        for (int mb = 0; mb < 2; mb++) {
            const int cA = o0 + mb * 16 + gid, cB = cA + 8;
#pragma unroll
            for (int nb = 0; nb < 8; nb++) {
                float sA = acc[mb][nb][0] + acc[mb][nb][1];
                float sB = acc[mb][nb][2] + acc[mb][nb][3];
                sA += __shfl_xor_sync(0xffffffffu, sA, 1);
                sB += __shfl_xor_sync(0xffffffffu, sB, 1);
                if ((tg & 1) == 0) {
                    int n = nbase + (nb << 1) + (tg >> 1);
                    atomicAdd(dstp + (((size_t)(b * 32 + (cA >> 2)) * 1024 + n) << 2)
                                   + (cA & 3), sA);
                    atomicAdd(dstp + (((size_t)(b * 32 + (cB >> 2)) * 1024 + n) << 2)
                                   + (cB & 3), sB);
                }
            }
        }
    } else {
        float* Zs = sm;                      // 128 x 136 = 17408 < SB_OFF
#pragma unroll
        for (int mb = 0; mb < 2; mb++) {
            const int r = o0 + mb * 16 + gid;
#pragma unroll
            for (int nb = 0; nb < 8; nb++) {
                int col = sbase + nb * 8 + (tg << 1);
                *(float2*)&Zs[r * XP_ + col]       = make_float2(acc[mb][nb][0], acc[mb][nb][1]);
                *(float2*)&Zs[(r + 8) * XP_ + col] = make_float2(acc[mb][nb][2], acc[mb][nb][3]);
            }
        }
    }

    // ---- fused GroupNorm partial stats
#pragma unroll
    for (int mb = 0; mb < 2; mb++)
#pragma unroll
        for (int hi = 0; hi < 2; hi++) {
            float s = 0.f, s2 = 0.f;
#pragma unroll
            for (int nb = 0; nb < 8; nb++) {
                float v0 = acc[mb][nb][hi * 2 + 0];
                float v1 = acc[mb][nb][hi * 2 + 1];
                s += v0 + v1;
                s2 = fmaf(v0, v0, s2); s2 = fmaf(v1, v1, s2);
            }
            s  += __shfl_xor_sync(0xffffffffu, s, 1);
            s  += __shfl_xor_sync(0xffffffffu, s, 2);
            s2 += __shfl_xor_sync(0xffffffffu, s2, 1);
            s2 += __shfl_xor_sync(0xffffffffu, s2, 2);
            if (tg == 0) {
                int idx = (((warp << 3) | gid) << 3) | (mb << 2) | (hi << 1);
                sbuf[idx]     = s;
                sbuf[idx + 1] = s2;
            }
        }
    __syncthreads();

    if (pr == 2) {
        const float* Zs = sm;
#pragma unroll
        for (int j = 0; j < 16; j++) {
            int e = tid + (j << 8);
            int c = e >> 5, xs4 = e & 31;
            int xs = xs4 << 2;
            float4 v = *(const float4*)&Zs[c * XP_ + xs];
            float4 r = make_float4(
                __uint_as_float(tf32r(v.x)), __uint_as_float(tf32r(v.y)),
                __uint_as_float(tf32r(v.z)), __uint_as_float(tf32r(v.w)));
            int hh = hh0 + (xs >> 6);
            int sy = hh & 3;
            int xq = (xs & 63) >> 2;
            *(float4*)&g_vp[b][c >> 2][nbase + xq][((c & 3) << 4) + (sy << 2)] = r;
        }
    }
    if (tid < 64) {
        int grp = tid >> 1, v = tid & 1;
        float tot = 0.f;
#pragma unroll
        for (int ci = 0; ci < 4; ci++) {
            int ch = (grp << 2) + ci;
            int cow = ch >> 5, r = ch & 31;
            int cmb = r >> 4, chi = (r >> 3) & 1, cgid = r & 7;
#pragma unroll
            for (int csw = 0; csw < 2; csw++) {
                int w2 = (cow << 1) | csw;
                tot += sbuf[(((w2 << 3) | cgid) << 3) | (cmb << 2) | (chi << 1) | v];
            }
        }
        atomicAdd(&g_stat[pr][b][grp][v], tot);
    }
}

// ================= K2: finalize stats -> per-channel affine ================
__global__ void finalize_stats(
    const float* __restrict__ gqg, const float* __restrict__ gqb,
    const float* __restrict__ gkg, const float* __restrict__ gkb,
    const float* __restrict__ gvg, const float* __restrict__ gvb) {   // <<<1,192>>>
    int i = threadIdx.x;
    int pr = i >> 6, r = i & 63, b = r >> 5, grp = r & 31;
    float s  = g_stat[pr][b][grp][0];
    float s2 = g_stat[pr][b][grp][1];
    float mean = s * (1.f / 65536.f);
    float var  = s2 * (1.f / 65536.f) - mean * mean;
    float rstd = rsqrtf(var + EPS_);
    const float* ga = (pr == 0) ? gqg : ((pr == 1) ? gkg : gvg);
    const float* be = (pr == 0) ? gqb : ((pr == 1) ? gkb : gvb);
#pragma unroll
    for (int d = 0; d < 4; d++) {
        int c = (grp << 2) + d;
        float a = rstd * ga[c];
        g_aff[pr][b][c][0] = a;
        g_aff[pr][b][c][1] = be[c] - mean * a;
    }
}

// ================= K3: fused tensor-core patch attention ===================
// QK logits ALSO on tensor cores: one m16n8k8 tf32 MMA per 8-key sub with
// A = q rows (dims 0-3, slots a2/a3 = 0), B = K^T from ks4 (1 LDS.32,
// b1 = b0 since A's upper k-slots are zero), C = gathered rel-pos biases
// (the MMA adds them for free). D-frag = biased logits on the SAME thread
// layout as before: thread (gid,tg) owns rows {gid,gid+8} x keys {2tg,2tg+1}.
// AV MMA uses key permutation sigma=[0,2,4,6,1,3,5,7]: A slots (a0,a1)=key
// 2tg, (a2,a3)=key 2tg+1; V B-frag rows mk+2tg / mk+2tg+1 (pitch 68 ->
// banks 8tg+8j+gid, conflict-free). Output layout unchanged.
#define VSP_    68
#define VS_BUF  (64 * VSP_)                 // 4352 floats per stage
#define SM_TAB  0
#define SM_K    6728                        // 1024 float4
#define SM_KC   (SM_K + 4096)               // 1024 ints (8B aligned)
#define SM_VS   (SM_KC + 1024)              // 3 * 4352
#define ATTN_SMEM_FLOATS (SM_VS + 3 * VS_BUF)
#define ATTN_SMEM_BYTES (ATTN_SMEM_FLOATS * 4)

__global__ __launch_bounds__(256, 2) void attn_kernel(
    const float* __restrict__ rel_table, float* __restrict__ out) {
    extern __shared__ float sm[];
    float*  tab  = sm + SM_TAB;
    float4* ks4  = (float4*)(sm + SM_K);
    int*    kc   = (int*)(sm + SM_KC);
    float*  vsb0 = sm + SM_VS;

    const int b = blockIdx.z, g = blockIdx.y;
    const int n0 = blockIdx.x << 7;
    const int tid = threadIdx.x;

    // ---- kick off V chunks 0 and 1 immediately
#pragma unroll
    for (int st = 0; st < 2; st++) {
        const float* vsrc = &g_vp[b][g][st << 6][0];
        float* vdst = vsb0 + st * VS_BUF;
#pragma unroll
        for (int j = 0; j < 4; j++) {
            int idx = tid + 256 * j;
            int row = idx >> 4, seg = idx & 15;
            cp16(vdst + row * VSP_ + seg * 4, vsrc + row * 64 + seg * 4);
        }
        cp_commit();
    }

    // ---- load bias table (scaled by log2e) and normalized K + kc
    for (int i = tid; i < TABSZ; i += 256)
        tab[i] = rel_table[g * TABSZ + i] * LOG2E_;
    const float* afk = &g_aff[1][b][g << 2][0];
    float4 afk0 = *(const float4*)afk;
    float4 afk1 = *(const float4*)(afk + 4);
    for (int i = tid; i < 1024; i += 256) {
        float4 kr = *(const float4*)&g_kp[b][g][i][0];
        float4 kk;
        kk.x = fmaf(kr.x * 0.0625f, afk0.x, afk0.y);
        kk.y = fmaf(kr.y * 0.0625f, afk0.z, afk0.w);
        kk.z = fmaf(kr.z * 0.0625f, afk1.x, afk1.y);
        kk.w = fmaf(kr.w * 0.0625f, afk1.z, afk1.w);
        ks4[i] = kk;
        kc[i]  = 961 * (i >> 8) + 31 * ((i >> 4) & 15) + (i & 15);
    }

    // ---- per-thread identity; q: single component (dim = tg) per row
    const int warp = tid >> 5, lane = tid & 31;
    const int gid = lane >> 2, tg = lane & 3;
    const int r0 = (warp << 4) + gid;
    const int nq0 = n0 + r0, nq1 = nq0 + 8;
    const float HS = 0.5f * LOG2E_;
    const float aQ = g_aff[0][b][(g << 2) + tg][0];
    const float bQ = g_aff[0][b][(g << 2) + tg][1];
    const unsigned aq0 = __float_as_uint(
        fmaf(g_qp[b][g][nq0][tg] * 0.0625f, aQ, bQ) * HS);
    const unsigned aq1 = __float_as_uint(
        fmaf(g_qp[b][g][nq1][tg] * 0.0625f, aQ, bQ) * HS);
    const int cn0 = 961 * (nq0 >> 8) + 31 * ((nq0 >> 4) & 15) + (nq0 & 15) + 3363;
    const int cn1 = 961 * (nq1 >> 8) + 31 * ((nq1 >> 4) & 15) + (nq1 & 15) + 3363;
    const float* kss = (const float*)ks4;

    float acc[8][4];
#pragma unroll
    for (int j = 0; j < 8; j++)
#pragma unroll
        for (int i = 0; i < 4; i++) acc[j][i] = 0.f;
    float wsum0 = 0.f, wsum1 = 0.f;

    // ---- main loop: 16 chunks of 64 keys, 3-stage cp.async ring
    for (int mc = 0; mc < 16; mc++) {
        if (mc < 15) cp_wait1(); else cp_wait0();
        __syncthreads();                    // also orders tab/ks/kc writes
        if (mc + 2 < 16) {
            const float* vsrc = &g_vp[b][g][(mc + 2) << 6][0];
            float* vdst = vsb0 + ((mc + 2) % 3) * VS_BUF;
#pragma unroll
            for (int j = 0; j < 4; j++) {
                int idx = tid + 256 * j;
                int row = idx >> 4, seg = idx & 15;
                cp16(vdst + row * VSP_ + seg * 4, vsrc + row * 64 + seg * 4);
            }
            cp_commit();
        }
        const float* vsb = vsb0 + (mc % 3) * VS_BUF;
        const int m0 = mc << 6;

#pragma unroll
        for (int sub = 0; sub < 8; sub++) {
            const int mk = m0 + (sub << 3);
            // biases as the MMA C-operand (d-layout: rows gid/gid+8, keys 2tg/2tg+1)
            int2 kcp = *(const int2*)&kc[mk + (tg << 1)];
            float d[4];
            d[0] = tab[cn0 - kcp.x];
            d[1] = tab[cn0 - kcp.y];
            d[2] = tab[cn1 - kcp.x];
            d[3] = tab[cn1 - kcp.y];
            // K B-frag: one scalar (banks 4*gid+tg); b1 slot hits zero A slots
            unsigned bk = __float_as_uint(kss[((mk + gid) << 2) + tg]);
            mma_tf32(d, aq0, aq1, 0u, 0u, bk, bk);

            float w00 = ex2f(d[0]);     // (row nq0, key 2tg)
            float w01 = ex2f(d[1]);     // (row nq0, key 2tg+1)
            float w10 = ex2f(d[2]);     // (row nq1, key 2tg)
            float w11 = ex2f(d[3]);
            wsum0 += w00 + w01;
            wsum1 += w10 + w11;

            unsigned a0 = __float_as_uint(w00), a1 = __float_as_uint(w10);
            unsigned a2 = __float_as_uint(w01), a3 = __float_as_uint(w11);

            // V B-frags under sigma: rows mk+2tg, mk+2tg+1
            const float* vr0 = vsb + ((sub << 3) + (tg << 1)) * VSP_ + gid;
            const float* vr1 = vr0 + VSP_;
#pragma unroll
            for (int j = 0; j < 8; j++) {
                unsigned b0 = __float_as_uint(vr0[8 * j]);
                unsigned b1 = __float_as_uint(vr1[8 * j]);
                mma_tf32(acc[j], a0, a1, a2, a3, b0, b1);
            }
        }
    }

    // ---- exact row sums, deferred V affine, epilogue
    wsum0 += __shfl_xor_sync(0xffffffffu, wsum0, 1);
    wsum0 += __shfl_xor_sync(0xffffffffu, wsum0, 2);
    wsum1 += __shfl_xor_sync(0xffffffffu, wsum1, 1);
    wsum1 += __shfl_xor_sync(0xffffffffu, wsum1, 2);
    const float inv0 = 1.f / wsum0, inv1 = 1.f / wsum1;

    float avA[4], avB[4];
#pragma unroll
    for (int dd = 0; dd < 4; dd++) {
        avA[dd] = g_aff[2][b][(g << 2) + dd][0];
        avB[dd] = g_aff[2][b][(g << 2) + dd][1];
    }

    const int t0 = nq0 >> 8, y0 = (nq0 >> 4) & 15, x0 = nq0 & 15;
    const int t1 = nq1 >> 8, y1 = (nq1 >> 4) & 15, x1 = nq1 & 15;
    const size_t ob0 = ((size_t)(b * C_) + (g << 2)) * S_
                     + t0 * 4096 + (y0 << 2) * 64 + (x0 << 2);
    const size_t ob1 = ((size_t)(b * C_) + (g << 2)) * S_
                     + t1 * 4096 + (y1 << 2) * 64 + (x1 << 2);
#pragma unroll
    for (int j = 0; j < 8; j++) {
        int col = 8 * j + 2 * tg;
        int dd = col >> 4, p = col & 15;
        int sy = p >> 2, sx = p & 3;
        size_t off = (size_t)dd * S_ + sy * 64 + sx;
        *(float2*)&out[ob0 + off] = make_float2(
            fmaf(acc[j][0] * inv0, avA[dd], avB[dd]),
            fmaf(acc[j][1] * inv0, avA[dd], avB[dd]));
        *(float2*)&out[ob1 + off] = make_float2(
            fmaf(acc[j][2] * inv1, avA[dd], avB[dd]),
            fmaf(acc[j][3] * inv1, avA[dd], avB[dd]));
    }
}

// ================= launch ==================================================
extern "C" void kernel_launch(void* const* d_in, const int* in_sizes, int n_in,
                              void* d_out, int out_size) {
    const float* x   = (const float*)d_in[0];
    const float* Wq  = (const float*)d_in[1];
    const float* Wk  = (const float*)d_in[2];
    const float* Wv  = (const float*)d_in[3];
    const float* gqg = (const float*)d_in[4];
    const float* gqb = (const float*)d_in[5];
    const float* gkg = (const float*)d_in[6];
    const float* gkb = (const float*)d_in[7];
    const float* gvg = (const float*)d_in[8];
    const float* gvb = (const float*)d_in[9];
    const float* rel_table = (const float*)d_in[10];
    // d_in[11] = rel_index: unused (computed analytically in-kernel)
    float* out = (float*)d_out;

    cudaFuncSetAttribute(proj_kernel, cudaFuncAttributeMaxDynamicSharedMemorySize,
                         PROJ_SMEM_BYTES);
    cudaFuncSetAttribute(attn_kernel, cudaFuncAttributeMaxDynamicSharedMemorySize,
                         ATTN_SMEM_BYTES);

    zero_kernel<<<512, 256>>>();
    split_w_kernel<<<96, 256>>>(Wq, Wk, Wv);
    split_x_kernel<<<2048, 256>>>(x);
    proj_kernel<<<dim3(128, 2, 3), 256, PROJ_SMEM_BYTES>>>();
    finalize_stats<<<1, 192>>>(gqg, gqb, gkg, gkb, gvg, gvb);
    attn_kernel<<<dim3(8, 32, 2), 256, ATTN_SMEM_BYTES>>>(rel_table, out);
}